// round 10
// baseline (speedup 1.0000x reference)
#include <cuda_runtime.h>
#include <cuda_fp16.h>
#include <cstdint>

// Problem constants (fixed by dataset shapes)
#define KCODES 1024
#define DDIM   64
#define HW     4096
#define NPTS   65536
#define NELEM  4194304

#define TILE_N  64             // points per CTA (fine quanta -> tiny wave tail)
#define NTHREADS 128           // 4 warps x 16 points
#define CHUNK_K 64             // codes per B chunk
#define NCHUNK  16

// Output layout (floats), concatenated in reference return order
#define OFF_EK   0
#define OFF_IDX  4194304
#define OFF_L    4259840
#define OFF_CB   4259841
#define OFF_CNT  4325377
#define OFF_SUM  4326401

#define DECAY 0.99f
#define OMD   0.01f
#define EPSV  1e-5f

// SMEM byte offsets (dynamic smem)
#define SM_ZS    0          // [64][64] f32 z staging         16384 B
#define SM_CN    16384      // 1024 f32 code norms             4096 B
#define SM_IDX   20480      // 64 int indices                   256 B
#define SM_B     20736      // 2 bufs x (hi 9216 + lo 9216)   36864 B
#define SM_BYTES 57600
#define B_BUF_BYTES 18432   // one buffer (hi part + lo part)
#define B_PART_WORDS 2304   // 9216 / 4
#define B_ROW_WORDS 36      // 32 data words (64 f16) + 4 pad -> conflict-free

// Scratch globals (no allocation allowed). fp16 hi + fp16 residual lo.
__device__ __align__(16) __half g_cbhi[KCODES * DDIM];
__device__ __align__(16) __half g_cblo[KCODES * DDIM];
__device__ float g_cnorm[KCODES];
__device__ float g_counts[KCODES];
__device__ float g_sums[KCODES * DDIM];
__device__ float g_cs[KCODES];          // count_s from finalize_a
__device__ float g_loss;

// ---------------------------------------------------------------------------
__device__ __forceinline__ uint32_t smem_u32(const void* p) {
    uint32_t a;
    asm("{ .reg .u64 t; cvta.to.shared.u64 t, %1; cvt.u32.u64 %0, t; }"
        : "=r"(a) : "l"(p));
    return a;
}
__device__ __forceinline__ uint32_t pack_h2(float x, float y) {
    __half2 h = __floats2half2_rn(x, y);
    return *(uint32_t*)&h;
}
__device__ __forceinline__ void mma_f16(float& c0, float& c1, float& c2, float& c3,
                                        uint32_t a0, uint32_t a1, uint32_t a2,
                                        uint32_t a3, uint32_t b0, uint32_t b1) {
    asm volatile(
        "mma.sync.aligned.m16n8k16.row.col.f32.f16.f16.f32 "
        "{%0,%1,%2,%3}, {%4,%5,%6,%7}, {%8,%9}, {%0,%1,%2,%3};"
        : "+f"(c0), "+f"(c1), "+f"(c2), "+f"(c3)
        : "r"(a0), "r"(a1), "r"(a2), "r"(a3), "r"(b0), "r"(b1));
}
__device__ __forceinline__ void cp_async16(uint32_t dst, const void* src) {
    asm volatile("cp.async.ca.shared.global [%0], [%1], 16;"
                 :: "r"(dst), "l"(src));
}
__device__ __forceinline__ void cp_commit() {
    asm volatile("cp.async.commit_group;");
}
__device__ __forceinline__ void cp_wait_all() {
    asm volatile("cp.async.wait_group 0;");
}

// ---------------------------------------------------------------------------
// Kernel A: split codebook into fp16 hi/lo, exact f32 norms, zero scratch.
// ---------------------------------------------------------------------------
__global__ void prep_kernel(const float* __restrict__ cb) {
    __shared__ float s8[8];
    int t = blockIdx.x * blockDim.x + threadIdx.x;   // 0..65535
    float v = cb[t];
    __half hi = __float2half_rn(v);
    g_cbhi[t] = hi;
    g_cblo[t] = __float2half_rn(v - __half2float(hi));
    g_sums[t] = 0.0f;

    float sq = v * v;
#pragma unroll
    for (int off = 16; off; off >>= 1)
        sq += __shfl_down_sync(0xffffffffu, sq, off);
    if ((threadIdx.x & 31) == 0) s8[threadIdx.x >> 5] = sq;
    __syncthreads();
    if (threadIdx.x < 4) {
        int kk = (blockIdx.x << 2) + threadIdx.x;
        g_counts[kk] = 0.0f;
        g_cnorm[kk] = s8[2 * threadIdx.x] + s8[2 * threadIdx.x + 1];
    }
    if (t == 0) g_loss = 0.0f;
}

// ---------------------------------------------------------------------------
// Kernel B: fp16-split m16n8k16 distance GEMM + argmin + epilogue
// 1024 CTAs x 128 threads (occ 3); CTA = 64 points x 1024 codes.
// Warp w owns points [16w, 16w+16); A (z hi/lo) lives in registers.
// Two n8-tiles per iteration -> 2 independent accumulator chains.
// ---------------------------------------------------------------------------
__global__ __launch_bounds__(NTHREADS, 3)
void vq_main(const float* __restrict__ z, const float* __restrict__ cb,
             float* __restrict__ out) {
    extern __shared__ float sm[];
    char* smb = (char*)sm;
    float* zs   = sm;                       // [64][64] f32
    float* cn_s = (float*)(smb + SM_CN);
    int*   idxs = (int*)(smb + SM_IDX);
    const uint32_t sbase = smem_u32(sm);

    const int tid  = threadIdx.x;
    const int w    = tid >> 5;
    const int lane = tid & 31;
    const int g    = lane >> 2;             // 0..7  (point row / B code col)
    const int q    = lane & 3;              // 0..3  (k pair / D col pair)
    const int pb   = w * 16;

    const int base = blockIdx.x * TILE_N;
    const int b    = base >> 12;
    const int rem  = base & 4095;
    const float* zbase = z + (size_t)b * (DDIM * HW) + rem;

    // load z tile [c][p] coalesced + code norms
    for (int i = tid; i < (DDIM * TILE_N) / 4; i += NTHREADS) {
        int lin = i * 4;
        int c = lin >> 6;
        int p = lin & 63;
        *(float4*)(zs + c * TILE_N + p) = *(const float4*)(zbase + c * HW + p);
    }
    for (int i = tid; i < KCODES; i += NTHREADS) cn_s[i] = g_cnorm[i];

    // prefetch B chunk: hi/lo fp16, per code row = 32 data words + 4 pad
    auto prefetch = [&](int buf, int k0) {
#pragma unroll
        for (int it = 0; it < 8; it++) {
            int u    = tid + it * NTHREADS;     // 0..1023
            int part = u >> 9;
            int u2   = u & 511;
            int code = u2 >> 3;                 // 0..63
            int g16  = u2 & 7;                  // 16B granule in row
            const __half* src =
                (part ? g_cblo : g_cbhi) + (k0 + code) * DDIM + g16 * 8;
            uint32_t dst = sbase + SM_B + buf * B_BUF_BYTES + part * 9216
                         + code * (B_ROW_WORDS * 4) + g16 * 16;
            cp_async16(dst, src);
        }
        cp_commit();
    };
    prefetch(0, 0);
    __syncthreads();   // zs ready

    // Build A fragments in registers: 4 k16-steps x 4 regs x {hi,lo}
    uint32_t ahi[4][4], alo[4][4];
    const int p0 = pb + g, p1 = pb + g + 8;
#pragma unroll
    for (int kk = 0; kk < 4; kk++) {
#pragma unroll
        for (int half = 0; half < 2; half++) {   // 0: k-low pair, 1: k-high (+8)
            int c0 = kk * 16 + 2 * q + half * 8;
            float x0 = zs[c0 * TILE_N + p0];
            float y0 = zs[(c0 + 1) * TILE_N + p0];
            float x1 = zs[c0 * TILE_N + p1];
            float y1 = zs[(c0 + 1) * TILE_N + p1];
            float hx0 = __half2float(__float2half_rn(x0));
            float hy0 = __half2float(__float2half_rn(y0));
            float hx1 = __half2float(__float2half_rn(x1));
            float hy1 = __half2float(__float2half_rn(y1));
            ahi[kk][half * 2]     = pack_h2(hx0, hy0);
            ahi[kk][half * 2 + 1] = pack_h2(hx1, hy1);
            alo[kk][half * 2]     = pack_h2(x0 - hx0, y0 - hy0);
            alo[kk][half * 2 + 1] = pack_h2(x1 - hx1, y1 - hy1);
        }
    }

    float bd0 = 1e30f, bd1 = 1e30f;
    int   bi0 = 0,     bi1 = 0;

    for (int c = 0; c < NCHUNK; c++) {
        const int buf = c & 1;
        cp_wait_all();
        __syncthreads();                     // chunk c in smem; prev compute done
        if (c < NCHUNK - 1) prefetch(buf ^ 1, (c + 1) * CHUNK_K);

        const uint32_t* Bh = (const uint32_t*)(smb + SM_B + buf * B_BUF_BYTES);
        const uint32_t* Bl = Bh + B_PART_WORDS;

#pragma unroll 1
        for (int t = 0; t < 8; t += 2) {     // 2 n8-tiles per iteration
            float u0 = 0.f, u1 = 0.f, u2 = 0.f, u3 = 0.f;   // tile t
            float v0 = 0.f, v1 = 0.f, v2 = 0.f, v3 = 0.f;   // tile t+1
            const int woA = (t * 8 + g) * B_ROW_WORDS + q;
            const int woB = woA + 8 * B_ROW_WORDS;
#pragma unroll
            for (int kk = 0; kk < 4; kk++) {
                uint32_t Ah0 = Bh[woA + kk * 8];
                uint32_t Ah1 = Bh[woA + kk * 8 + 4];
                uint32_t Al0 = Bl[woA + kk * 8];
                uint32_t Al1 = Bl[woA + kk * 8 + 4];
                uint32_t Bh0 = Bh[woB + kk * 8];
                uint32_t Bh1 = Bh[woB + kk * 8 + 4];
                uint32_t Bl0 = Bl[woB + kk * 8];
                uint32_t Bl1 = Bl[woB + kk * 8 + 4];
                mma_f16(u0, u1, u2, u3, ahi[kk][0], ahi[kk][1], ahi[kk][2],
                        ahi[kk][3], Ah0, Ah1);
                mma_f16(v0, v1, v2, v3, ahi[kk][0], ahi[kk][1], ahi[kk][2],
                        ahi[kk][3], Bh0, Bh1);
                mma_f16(u0, u1, u2, u3, ahi[kk][0], ahi[kk][1], ahi[kk][2],
                        ahi[kk][3], Al0, Al1);
                mma_f16(v0, v1, v2, v3, ahi[kk][0], ahi[kk][1], ahi[kk][2],
                        ahi[kk][3], Bl0, Bl1);
                mma_f16(u0, u1, u2, u3, alo[kk][0], alo[kk][1], alo[kk][2],
                        alo[kk][3], Ah0, Ah1);
                mma_f16(v0, v1, v2, v3, alo[kk][0], alo[kk][1], alo[kk][2],
                        alo[kk][3], Bh0, Bh1);
            }
            // acc layout: 0=(g,2q) 1=(g,2q+1) 2=(g+8,2q) 3=(g+8,2q+1)
            {
                const int ck = c * CHUNK_K + t * 8;
                float n0 = cn_s[ck + 2 * q];
                float n1 = cn_s[ck + 2 * q + 1];
                float d;
                d = n0 - 2.0f * u0; if (d < bd0) { bd0 = d; bi0 = ck + 2 * q; }
                d = n1 - 2.0f * u1; if (d < bd0) { bd0 = d; bi0 = ck + 2 * q + 1; }
                d = n0 - 2.0f * u2; if (d < bd1) { bd1 = d; bi1 = ck + 2 * q; }
                d = n1 - 2.0f * u3; if (d < bd1) { bd1 = d; bi1 = ck + 2 * q + 1; }
            }
            {
                const int ck = c * CHUNK_K + (t + 1) * 8;
                float n0 = cn_s[ck + 2 * q];
                float n1 = cn_s[ck + 2 * q + 1];
                float d;
                d = n0 - 2.0f * v0; if (d < bd0) { bd0 = d; bi0 = ck + 2 * q; }
                d = n1 - 2.0f * v1; if (d < bd0) { bd0 = d; bi0 = ck + 2 * q + 1; }
                d = n0 - 2.0f * v2; if (d < bd1) { bd1 = d; bi1 = ck + 2 * q; }
                d = n1 - 2.0f * v3; if (d < bd1) { bd1 = d; bi1 = ck + 2 * q + 1; }
            }
        }
    }

    // reduce argmin across the 4 q-lanes of each point row
#pragma unroll
    for (int off = 1; off <= 2; off <<= 1) {
        float od = __shfl_xor_sync(0xffffffffu, bd0, off);
        int   oi = __shfl_xor_sync(0xffffffffu, bi0, off);
        if (od < bd0 || (od == bd0 && oi < bi0)) { bd0 = od; bi0 = oi; }
        od = __shfl_xor_sync(0xffffffffu, bd1, off);
        oi = __shfl_xor_sync(0xffffffffu, bi1, off);
        if (od < bd1 || (od == bd1 && oi < bi1)) { bd1 = od; bi1 = oi; }
    }
    if (q == 0) {
        idxs[pb + g]     = bi0;
        idxs[pb + g + 8] = bi1;
        out[OFF_IDX + base + pb + g]     = (float)bi0;
        out[OFF_IDX + base + pb + g + 8] = (float)bi1;
    }
    __syncthreads();

    // ------------- epilogue: hist, e_k, loss, EMA stats -------------
    int* hist = (int*)(smb + SM_B);          // alias B region
    for (int i = tid; i < KCODES; i += NTHREADS) hist[i] = 0;
    __syncthreads();
    if (tid < TILE_N) atomicAdd(&hist[idxs[tid]], 1);
    __syncthreads();

    for (int i = tid; i < KCODES; i += NTHREADS) {
        int v = hist[i];
        if (v) atomicAdd(&g_counts[i], (float)v);
    }

    float* ekbase = out + OFF_EK + (size_t)b * (DDIM * HW) + rem;
    float sse = 0.0f;
    for (int i = tid; i < DDIM * TILE_N; i += NTHREADS) {
        int cc = i >> 6;
        int p  = i & 63;
        int kk = idxs[p];
        float cv = cb[kk * DDIM + cc];
        float zv = zs[cc * TILE_N + p];
        ekbase[cc * HW + p] = cv;            // coalesced in p
        float dlt = zv - cv;
        sse += dlt * dlt;
        atomicAdd(&g_sums[kk * DDIM + cc], zv);
    }
#pragma unroll
    for (int off = 16; off; off >>= 1)
        sse += __shfl_down_sync(0xffffffffu, sse, off);
    if ((tid & 31) == 0) atomicAdd(&g_loss, sse);
}

// ---------------------------------------------------------------------------
// Kernel C1: counts, n-reduction, count_s, loss (1 CTA, 1024 threads — tiny)
// ---------------------------------------------------------------------------
__global__ void finalize_a(const float* __restrict__ ema_count,
                           float* __restrict__ out) {
    __shared__ float warp_s[32];
    __shared__ float n_s;
    int t = threadIdx.x;

    float nc = ema_count[t] * DECAY + OMD * g_counts[t];
    out[OFF_CNT + t] = nc;

    float v = nc;
#pragma unroll
    for (int off = 16; off; off >>= 1)
        v += __shfl_down_sync(0xffffffffu, v, off);
    if ((t & 31) == 0) warp_s[t >> 5] = v;
    __syncthreads();
    if (t == 0) {
        float n = 0.0f;
#pragma unroll
        for (int w = 0; w < 32; w++) n += warp_s[w];
        n_s = n;
        out[OFF_L] = 1.25f * g_loss * (1.0f / (float)NELEM);
    }
    __syncthreads();
    float n = n_s;
    g_cs[t] = (nc + EPSV) / (n + (float)KCODES * EPSV) * n;
}

// ---------------------------------------------------------------------------
// Kernel C2: new_sum + codebook (grid-parallel; 256 CTAs x 256 threads)
// ---------------------------------------------------------------------------
__global__ void finalize_b(const float* __restrict__ ema_sum,
                           float* __restrict__ out) {
    int i = blockIdx.x * blockDim.x + threadIdx.x;   // 0..65535
    int k = i >> 6;
    float ns = ema_sum[i] * DECAY + OMD * g_sums[i];
    out[OFF_SUM + i] = ns;
    out[OFF_CB + i]  = ns / g_cs[k];
}

// ---------------------------------------------------------------------------
extern "C" void kernel_launch(void* const* d_in, const int* in_sizes, int n_in,
                              void* d_out, int out_size) {
    (void)in_sizes; (void)n_in; (void)out_size;
    const float* z         = (const float*)d_in[0];
    const float* cb        = (const float*)d_in[1];
    const float* ema_count = (const float*)d_in[2];
    const float* ema_sum   = (const float*)d_in[3];
    float* out = (float*)d_out;

    prep_kernel<<<256, 256>>>(cb);
    cudaFuncSetAttribute(vq_main, cudaFuncAttributeMaxDynamicSharedMemorySize,
                         SM_BYTES);
    vq_main<<<NPTS / TILE_N, NTHREADS, SM_BYTES>>>(z, cb, out);
    finalize_a<<<1, 1024>>>(ema_count, out);
    finalize_b<<<256, 256>>>(ema_sum, out);
}

// round 11
// speedup vs baseline: 1.4723x; 1.4723x over previous
#include <cuda_runtime.h>
#include <cuda_fp16.h>
#include <cstdint>

// Problem constants (fixed by dataset shapes)
#define KCODES 1024
#define DDIM   64
#define HW     4096
#define NPTS   65536
#define NELEM  4194304

#define TILE_N  128            // points per CTA
#define CHUNK_K 64             // codes per B chunk
#define NCHUNK  16

// Output layout (floats), concatenated in reference return order
#define OFF_EK   0
#define OFF_IDX  4194304
#define OFF_L    4259840
#define OFF_CB   4259841
#define OFF_CNT  4325377
#define OFF_SUM  4326401

#define DECAY 0.99f
#define OMD   0.01f
#define EPSV  1e-5f

// SMEM byte offsets (dynamic smem)
#define SM_ZS    0          // [64][128] f32 z staging        32768 B
#define SM_CN    32768      // 1024 f32 code norms             4096 B
#define SM_IDX   36864      // 128 int indices                  512 B
#define SM_B     37376      // 2 bufs x (hi 9216 + lo 9216)   36864 B
#define SM_BYTES 74240      // (SM_B region also reused as code-row stage: 33280 B)
#define B_BUF_BYTES 18432   // one buffer (hi part + lo part)
#define B_PART_WORDS 2304   // 9216 / 4
#define B_ROW_WORDS 36      // 32 data words (64 f16) + 4 pad -> conflict-free

// Scratch globals (no allocation allowed). fp16 hi + fp16 residual lo.
__device__ __align__(16) __half g_cbhi[KCODES * DDIM];
__device__ __align__(16) __half g_cblo[KCODES * DDIM];
__device__ float g_cnorm[KCODES];
__device__ float g_counts[KCODES];
__device__ float g_sums[KCODES * DDIM];
__device__ float g_cs[KCODES];          // count_s from finalize_a
__device__ float g_loss;

// ---------------------------------------------------------------------------
__device__ __forceinline__ uint32_t smem_u32(const void* p) {
    uint32_t a;
    asm("{ .reg .u64 t; cvta.to.shared.u64 t, %1; cvt.u32.u64 %0, t; }"
        : "=r"(a) : "l"(p));
    return a;
}
__device__ __forceinline__ uint32_t pack_h2(float x, float y) {
    __half2 h = __floats2half2_rn(x, y);
    return *(uint32_t*)&h;
}
__device__ __forceinline__ void mma_f16(float& c0, float& c1, float& c2, float& c3,
                                        uint32_t a0, uint32_t a1, uint32_t a2,
                                        uint32_t a3, uint32_t b0, uint32_t b1) {
    asm volatile(
        "mma.sync.aligned.m16n8k16.row.col.f32.f16.f16.f32 "
        "{%0,%1,%2,%3}, {%4,%5,%6,%7}, {%8,%9}, {%0,%1,%2,%3};"
        : "+f"(c0), "+f"(c1), "+f"(c2), "+f"(c3)
        : "r"(a0), "r"(a1), "r"(a2), "r"(a3), "r"(b0), "r"(b1));
}
__device__ __forceinline__ void cp_async16(uint32_t dst, const void* src) {
    asm volatile("cp.async.ca.shared.global [%0], [%1], 16;"
                 :: "r"(dst), "l"(src));
}
__device__ __forceinline__ void cp_commit() {
    asm volatile("cp.async.commit_group;");
}
__device__ __forceinline__ void cp_wait_all() {
    asm volatile("cp.async.wait_group 0;");
}

// ---------------------------------------------------------------------------
// Kernel A: split codebook into fp16 hi/lo, exact f32 norms, zero scratch.
// ---------------------------------------------------------------------------
__global__ void prep_kernel(const float* __restrict__ cb) {
    __shared__ float s8[8];
    int t = blockIdx.x * blockDim.x + threadIdx.x;   // 0..65535
    float v = cb[t];
    __half hi = __float2half_rn(v);
    g_cbhi[t] = hi;
    g_cblo[t] = __float2half_rn(v - __half2float(hi));
    g_sums[t] = 0.0f;

    float sq = v * v;
#pragma unroll
    for (int off = 16; off; off >>= 1)
        sq += __shfl_down_sync(0xffffffffu, sq, off);
    if ((threadIdx.x & 31) == 0) s8[threadIdx.x >> 5] = sq;
    __syncthreads();
    if (threadIdx.x < 4) {
        int kk = (blockIdx.x << 2) + threadIdx.x;
        g_counts[kk] = 0.0f;
        g_cnorm[kk] = s8[2 * threadIdx.x] + s8[2 * threadIdx.x + 1];
    }
    if (t == 0) g_loss = 0.0f;
}

// ---------------------------------------------------------------------------
// Kernel B: fp16-split m16n8k16 distance GEMM + argmin + epilogue
// 512 CTAs x 256 threads; CTA = 128 points x 1024 codes.
// Warp w owns points [16w, 16w+16); A (z hi/lo) lives in registers.
// Two n8-tiles per iteration -> 2 independent accumulator chains.
// ---------------------------------------------------------------------------
__global__ __launch_bounds__(256, 2)
void vq_main(const float* __restrict__ z, const float* __restrict__ cb,
             float* __restrict__ out) {
    extern __shared__ float sm[];
    char* smb = (char*)sm;
    float* zs   = sm;                       // [64][128] f32
    float* cn_s = (float*)(smb + SM_CN);
    int*   idxs = (int*)(smb + SM_IDX);
    const uint32_t sbase = smem_u32(sm);

    const int tid  = threadIdx.x;
    const int w    = tid >> 5;
    const int lane = tid & 31;
    const int g    = lane >> 2;             // 0..7  (point row / B code col)
    const int q    = lane & 3;              // 0..3  (k pair / D col pair)
    const int pb   = w * 16;

    const int base = blockIdx.x * TILE_N;
    const int b    = base >> 12;
    const int rem  = base & 4095;
    const float* zbase = z + (size_t)b * (DDIM * HW) + rem;

    // load z tile [c][p] coalesced + code norms
    for (int i = tid; i < (DDIM * TILE_N) / 4; i += 256) {
        int lin = i * 4;
        int c = lin >> 7;
        int p = lin & 127;
        *(float4*)(zs + c * TILE_N + p) = *(const float4*)(zbase + c * HW + p);
    }
    for (int i = tid; i < KCODES; i += 256) cn_s[i] = g_cnorm[i];

    // prefetch B chunk: hi/lo fp16, per code row = 32 data words + 4 pad
    auto prefetch = [&](int buf, int k0) {
#pragma unroll
        for (int it = 0; it < 4; it++) {
            int u    = tid + it * 256;          // 0..1023
            int part = u >> 9;
            int u2   = u & 511;
            int code = u2 >> 3;                 // 0..63
            int g16  = u2 & 7;                  // 16B granule in row
            const __half* src =
                (part ? g_cblo : g_cbhi) + (k0 + code) * DDIM + g16 * 8;
            uint32_t dst = sbase + SM_B + buf * B_BUF_BYTES + part * 9216
                         + code * (B_ROW_WORDS * 4) + g16 * 16;
            cp_async16(dst, src);
        }
        cp_commit();
    };
    prefetch(0, 0);
    __syncthreads();   // zs ready

    // Build A fragments in registers: 4 k16-steps x 4 regs x {hi,lo}
    uint32_t ahi[4][4], alo[4][4];
    const int p0 = pb + g, p1 = pb + g + 8;
#pragma unroll
    for (int kk = 0; kk < 4; kk++) {
#pragma unroll
        for (int half = 0; half < 2; half++) {   // 0: k-low pair, 1: k-high (+8)
            int c0 = kk * 16 + 2 * q + half * 8;
            float x0 = zs[c0 * TILE_N + p0];
            float y0 = zs[(c0 + 1) * TILE_N + p0];
            float x1 = zs[c0 * TILE_N + p1];
            float y1 = zs[(c0 + 1) * TILE_N + p1];
            float hx0 = __half2float(__float2half_rn(x0));
            float hy0 = __half2float(__float2half_rn(y0));
            float hx1 = __half2float(__float2half_rn(x1));
            float hy1 = __half2float(__float2half_rn(y1));
            ahi[kk][half * 2]     = pack_h2(hx0, hy0);
            ahi[kk][half * 2 + 1] = pack_h2(hx1, hy1);
            alo[kk][half * 2]     = pack_h2(x0 - hx0, y0 - hy0);
            alo[kk][half * 2 + 1] = pack_h2(x1 - hx1, y1 - hy1);
        }
    }

    float bd0 = 1e30f, bd1 = 1e30f;
    int   bi0 = 0,     bi1 = 0;

    for (int c = 0; c < NCHUNK; c++) {
        const int buf = c & 1;
        cp_wait_all();
        __syncthreads();                     // chunk c in smem; prev compute done
        if (c < NCHUNK - 1) prefetch(buf ^ 1, (c + 1) * CHUNK_K);

        const uint32_t* Bh = (const uint32_t*)(smb + SM_B + buf * B_BUF_BYTES);
        const uint32_t* Bl = Bh + B_PART_WORDS;

#pragma unroll 1
        for (int t = 0; t < 8; t += 2) {     // 2 n8-tiles per iteration
            float u0 = 0.f, u1 = 0.f, u2 = 0.f, u3 = 0.f;   // tile t
            float v0 = 0.f, v1 = 0.f, v2 = 0.f, v3 = 0.f;   // tile t+1
            const int woA = (t * 8 + g) * B_ROW_WORDS + q;
            const int woB = woA + 8 * B_ROW_WORDS;
#pragma unroll
            for (int kk = 0; kk < 4; kk++) {
                uint32_t Ah0 = Bh[woA + kk * 8];
                uint32_t Ah1 = Bh[woA + kk * 8 + 4];
                uint32_t Al0 = Bl[woA + kk * 8];
                uint32_t Al1 = Bl[woA + kk * 8 + 4];
                uint32_t Bh0 = Bh[woB + kk * 8];
                uint32_t Bh1 = Bh[woB + kk * 8 + 4];
                uint32_t Bl0 = Bl[woB + kk * 8];
                uint32_t Bl1 = Bl[woB + kk * 8 + 4];
                mma_f16(u0, u1, u2, u3, ahi[kk][0], ahi[kk][1], ahi[kk][2],
                        ahi[kk][3], Ah0, Ah1);
                mma_f16(v0, v1, v2, v3, ahi[kk][0], ahi[kk][1], ahi[kk][2],
                        ahi[kk][3], Bh0, Bh1);
                mma_f16(u0, u1, u2, u3, ahi[kk][0], ahi[kk][1], ahi[kk][2],
                        ahi[kk][3], Al0, Al1);
                mma_f16(v0, v1, v2, v3, ahi[kk][0], ahi[kk][1], ahi[kk][2],
                        ahi[kk][3], Bl0, Bl1);
                mma_f16(u0, u1, u2, u3, alo[kk][0], alo[kk][1], alo[kk][2],
                        alo[kk][3], Ah0, Ah1);
                mma_f16(v0, v1, v2, v3, alo[kk][0], alo[kk][1], alo[kk][2],
                        alo[kk][3], Bh0, Bh1);
            }
            // acc layout: 0=(g,2q) 1=(g,2q+1) 2=(g+8,2q) 3=(g+8,2q+1)
            {
                const int ck = c * CHUNK_K + t * 8;
                float n0 = cn_s[ck + 2 * q];
                float n1 = cn_s[ck + 2 * q + 1];
                float d;
                d = n0 - 2.0f * u0; if (d < bd0) { bd0 = d; bi0 = ck + 2 * q; }
                d = n1 - 2.0f * u1; if (d < bd0) { bd0 = d; bi0 = ck + 2 * q + 1; }
                d = n0 - 2.0f * u2; if (d < bd1) { bd1 = d; bi1 = ck + 2 * q; }
                d = n1 - 2.0f * u3; if (d < bd1) { bd1 = d; bi1 = ck + 2 * q + 1; }
            }
            {
                const int ck = c * CHUNK_K + (t + 1) * 8;
                float n0 = cn_s[ck + 2 * q];
                float n1 = cn_s[ck + 2 * q + 1];
                float d;
                d = n0 - 2.0f * v0; if (d < bd0) { bd0 = d; bi0 = ck + 2 * q; }
                d = n1 - 2.0f * v1; if (d < bd0) { bd0 = d; bi0 = ck + 2 * q + 1; }
                d = n0 - 2.0f * v2; if (d < bd1) { bd1 = d; bi1 = ck + 2 * q; }
                d = n1 - 2.0f * v3; if (d < bd1) { bd1 = d; bi1 = ck + 2 * q + 1; }
            }
        }
    }

    // reduce argmin across the 4 q-lanes of each point row
#pragma unroll
    for (int off = 1; off <= 2; off <<= 1) {
        float od = __shfl_xor_sync(0xffffffffu, bd0, off);
        int   oi = __shfl_xor_sync(0xffffffffu, bi0, off);
        if (od < bd0 || (od == bd0 && oi < bi0)) { bd0 = od; bi0 = oi; }
        od = __shfl_xor_sync(0xffffffffu, bd1, off);
        oi = __shfl_xor_sync(0xffffffffu, bi1, off);
        if (od < bd1 || (od == bd1 && oi < bi1)) { bd1 = od; bi1 = oi; }
    }
    if (q == 0) {
        idxs[pb + g]     = bi0;
        idxs[pb + g + 8] = bi1;
        out[OFF_IDX + base + pb + g]     = (float)bi0;
        out[OFF_IDX + base + pb + g + 8] = (float)bi1;
    }
    __syncthreads();   // idxs visible; all mainloop B reads complete

    // ------------- epilogue: counts, staged gather, e_k, loss, sums ------
    // direct global count atomics (REDG; no smem histogram)
    if (tid < TILE_N) atomicAdd(&g_counts[idxs[tid]], 1.0f);

    // stage the 128 chosen code rows into smem (alias B region), [p][65] pad
    float* cstage = (float*)(smb + SM_B);    // 128*65*4 = 33280 B <= 36864
    for (int i = tid; i < TILE_N * 16; i += 256) {   // 2048 float4 granules
        int p  = i >> 4;
        int f4 = (i & 15) * 4;
        float4 v4 = *(const float4*)(cb + (size_t)idxs[p] * DDIM + f4);
        float* dst = cstage + p * 65 + f4;
        dst[0] = v4.x; dst[1] = v4.y; dst[2] = v4.z; dst[3] = v4.w;
    }
    __syncthreads();

    float* ekbase = out + OFF_EK + (size_t)b * (DDIM * HW) + rem;
    float sse = 0.0f;
    for (int i = tid; i < DDIM * TILE_N; i += 256) {
        int cc = i >> 7;
        int p  = i & 127;
        float cv = cstage[p * 65 + cc];      // conflict-free: bank (p+cc)%32
        float zv = zs[cc * TILE_N + p];
        ekbase[cc * HW + p] = cv;            // coalesced in p
        float dlt = zv - cv;
        sse += dlt * dlt;
        atomicAdd(&g_sums[idxs[p] * DDIM + cc], zv);
    }
#pragma unroll
    for (int off = 16; off; off >>= 1)
        sse += __shfl_down_sync(0xffffffffu, sse, off);
    if ((tid & 31) == 0) atomicAdd(&g_loss, sse);
}

// ---------------------------------------------------------------------------
// Kernel C1: counts, n-reduction, count_s, loss (1 CTA, 1024 threads — tiny)
// ---------------------------------------------------------------------------
__global__ void finalize_a(const float* __restrict__ ema_count,
                           float* __restrict__ out) {
    __shared__ float warp_s[32];
    __shared__ float n_s;
    int t = threadIdx.x;

    float nc = ema_count[t] * DECAY + OMD * g_counts[t];
    out[OFF_CNT + t] = nc;

    float v = nc;
#pragma unroll
    for (int off = 16; off; off >>= 1)
        v += __shfl_down_sync(0xffffffffu, v, off);
    if ((t & 31) == 0) warp_s[t >> 5] = v;
    __syncthreads();
    if (t == 0) {
        float n = 0.0f;
#pragma unroll
        for (int w = 0; w < 32; w++) n += warp_s[w];
        n_s = n;
        out[OFF_L] = 1.25f * g_loss * (1.0f / (float)NELEM);
    }
    __syncthreads();
    float n = n_s;
    g_cs[t] = (nc + EPSV) / (n + (float)KCODES * EPSV) * n;
}

// ---------------------------------------------------------------------------
// Kernel C2: new_sum + codebook (grid-parallel; 256 CTAs x 256 threads)
// ---------------------------------------------------------------------------
__global__ void finalize_b(const float* __restrict__ ema_sum,
                           float* __restrict__ out) {
    int i = blockIdx.x * blockDim.x + threadIdx.x;   // 0..65535
    int k = i >> 6;
    float ns = ema_sum[i] * DECAY + OMD * g_sums[i];
    out[OFF_SUM + i] = ns;
    out[OFF_CB + i]  = ns / g_cs[k];
}

// ---------------------------------------------------------------------------
extern "C" void kernel_launch(void* const* d_in, const int* in_sizes, int n_in,
                              void* d_out, int out_size) {
    (void)in_sizes; (void)n_in; (void)out_size;
    const float* z         = (const float*)d_in[0];
    const float* cb        = (const float*)d_in[1];
    const float* ema_count = (const float*)d_in[2];
    const float* ema_sum   = (const float*)d_in[3];
    float* out = (float*)d_out;

    prep_kernel<<<256, 256>>>(cb);
    cudaFuncSetAttribute(vq_main, cudaFuncAttributeMaxDynamicSharedMemorySize,
                         SM_BYTES);
    vq_main<<<NPTS / TILE_N, 256, SM_BYTES>>>(z, cb, out);
    finalize_a<<<1, 1024>>>(ema_count, out);
    finalize_b<<<256, 256>>>(ema_sum, out);
}